// round 13
// baseline (speedup 1.0000x reference)
#include <cuda_runtime.h>
#include <cuda_bf16.h>
#include <cstdint>

#define DD 128
#define TM 128
#define TK 64
#define NTHREADS 512
#define GRID 148

// ---- device scratch (no allocations allowed) ----
__device__ double g_acc;
__device__ unsigned int g_done;
__device__ float g_a[4096];                    // ||sub_x_i||^2
__device__ float g_b[8192];                    // ||all_x_j||^2
__device__ __align__(16) __nv_bfloat16 g_Yt[128 * 8192];  // all_x^T bf16: [d][n]

// ---- dynamic smem layout (bytes) ----
#define Y_STAGE 16384                  // 128 rows * 128B bf16, XOR-swizzled
#define GB_SIZE 16384
#define SM_Y 0                         // 3 stages
#define SM_GB (3 * Y_STAGE)            // 2 buffers
#define SM_WSUM (SM_GB + 2 * GB_SIZE)
#define SMEM_TOTAL (SM_WSUM + 128)

// ---------------------------------------------------------------------------
static __device__ __forceinline__ uint32_t smem_u32(const void* p) {
    return (uint32_t)__cvta_generic_to_shared(p);
}
static __device__ __forceinline__ void cpa16(uint32_t smem_dst, const void* gsrc) {
    asm volatile("cp.async.cg.shared.global [%0], [%1], 16;\n" ::"r"(smem_dst), "l"(gsrc));
}
static __device__ __forceinline__ void cpa_commit() {
    asm volatile("cp.async.commit_group;\n" ::: "memory");
}
static __device__ __forceinline__ void ldsm_x4(uint32_t* r, uint32_t addr) {
    asm volatile("ldmatrix.sync.aligned.m8n8.x4.shared.b16 {%0,%1,%2,%3}, [%4];"
                 : "=r"(r[0]), "=r"(r[1]), "=r"(r[2]), "=r"(r[3]) : "r"(addr));
}

// ---------------------------------------------------------------------------
// prep: per-row sumsq -> g_a/g_b, bf16 transpose of all_x -> g_Yt.
// One block = 32 rows. Also zeros g_acc / g_done.
// ---------------------------------------------------------------------------
__global__ void prep_kernel(const float* __restrict__ subx,
                            const float* __restrict__ allx, int m, int n) {
    __shared__ float ys[32 * 132];
    int b = blockIdx.x;
    int t = threadIdx.x;
    if (b == 0 && t == 0) { g_acc = 0.0; g_done = 0u; }
    int nb_y = n / 32;
    bool isY = b < nb_y;
    const float* src = isY ? allx : subx;
    int r0 = isY ? b * 32 : (b - nb_y) * 32;

#pragma unroll
    for (int i = 0; i < 4; i++) {
        int ci = i * 256 + t;
        int rl = ci >> 5, c4 = ci & 31;
        float4 v = *(const float4*)(src + (size_t)(r0 + rl) * DD + c4 * 4);
        *(float4*)(ys + rl * 132 + c4 * 4) = v;
    }
    __syncthreads();

    {
        int rl = t >> 3, sub = t & 7;
        const float* row = ys + rl * 132 + sub * 16;
        float s = 0.f;
#pragma unroll
        for (int i = 0; i < 16; i++) { float v = row[i]; s += v * v; }
        s += __shfl_down_sync(0xffffffffu, s, 4, 8);
        s += __shfl_down_sync(0xffffffffu, s, 2, 8);
        s += __shfl_down_sync(0xffffffffu, s, 1, 8);
        if (sub == 0) { if (isY) g_b[r0 + rl] = s; else g_a[r0 + rl] = s; }
    }

    if (isY) {
        int d = t >> 1, half = t & 1;
        uint32_t pk[8];
#pragma unroll
        for (int i = 0; i < 8; i++) {
            int r = half * 16 + i * 2;
            float f0 = ys[r * 132 + d];
            float f1 = ys[(r + 1) * 132 + d];
            __nv_bfloat162 h = __float22bfloat162_rn(make_float2(f0, f1));
            pk[i] = *(uint32_t*)&h;
        }
        uint4* dst = (uint4*)(g_Yt + (size_t)d * n + r0 + half * 16);
        dst[0] = make_uint4(pk[0], pk[1], pk[2], pk[3]);
        dst[1] = make_uint4(pk[4], pk[5], pk[6], pk[7]);
    }
}

// ---------------------------------------------------------------------------
// main kernel: 512 threads, 16 warps (4/SMSP). Warp w = (qm 0..3, qn 0..1,
// kh 0..1): 32m x 64n output block, k-half of each 64-wide tile.
// Gpass: thread = (row = t>>2, chunk = t&3 -> 16 floats).
// ---------------------------------------------------------------------------
__global__ __launch_bounds__(NTHREADS, 1)
void main_kernel(const float* __restrict__ G, const float* __restrict__ X,
                 float* __restrict__ out, int m, int n) {
    extern __shared__ char smem[];
    const uint32_t sb = smem_u32(smem);
    float* wsum = (float*)(smem + SM_WSUM);

    const int t = threadIdx.x;
    const int bid = blockIdx.x;
    const int wid = t >> 5, lane = t & 31;
    const int g = lane >> 2, tg = lane & 3;
    const int qm = wid & 3, qn = (wid >> 2) & 1, kh = wid >> 3;
    const int kbase = kh * 32;
    const int rb = t >> 2, ch = t & 3;           // Gpass: row rb, float col ch*16

    const int U = (m / TM) * (n / TK);           // 4096
    const int base = U / GRID, rem = U - base * GRID;
    const int u0 = (bid < rem) ? bid * (base + 1)
                               : rem * (base + 1) + (bid - rem) * base;
    const int u1 = u0 + ((bid < rem) ? base + 1 : base);

    int cur_mt = u0 >> 7;
    int m0 = cur_mt * TM;

    float a_reg = g_a[m0 + rb];

    float acc[2][8][4];
#pragma unroll
    for (int i = 0; i < 2; i++)
#pragma unroll
        for (int j = 0; j < 8; j++)
#pragma unroll
            for (int c = 0; c < 4; c++) acc[i][j][c] = 0.f;
    float s_deg = 0.f, s_cross = 0.f;

    auto flush = [&]() {
#pragma unroll
        for (int ms = 0; ms < 2; ms++) {
            int r1 = m0 + qm * 32 + ms * 16 + g;
#pragma unroll
            for (int ns = 0; ns < 8; ns++) {
                int col = qn * 64 + ns * 8 + 2 * tg;
                float2 x0 = *(const float2*)(X + (size_t)r1 * DD + col);
                float2 x1 = *(const float2*)(X + (size_t)(r1 + 8) * DD + col);
                s_cross += acc[ms][ns][0] * x0.x + acc[ms][ns][1] * x0.y +
                           acc[ms][ns][2] * x1.x + acc[ms][ns][3] * x1.y;
                acc[ms][ns][0] = 0.f; acc[ms][ns][1] = 0.f;
                acc[ms][ns][2] = 0.f; acc[ms][ns][3] = 0.f;
            }
        }
    };

    auto issue_y = [&](int stage, int u) {
        int kk = (u & 127) * TK;
        uint32_t yv = sb + SM_Y + stage * Y_STAGE;
#pragma unroll
        for (int i = 0; i < 2; i++) {
            int ci = i * NTHREADS + t;
            int r = ci >> 3, c = ci & 7;
            cpa16(yv + r * 128 + ((c ^ (r & 7)) << 4),
                  g_Yt + (size_t)r * n + kk + c * 8);
        }
    };

    // G fp32: thread holds 16 floats of its row (one tile ahead)
    float4 gv[4];
    auto ldg_g = [&](int u) {
        int mm0 = (u >> 7) * TM;
        int kk = (u & 127) * TK;
        const float* p = G + (size_t)(mm0 + rb) * n + kk + ch * 16;
        gv[0] = *(const float4*)p;
        gv[1] = *(const float4*)(p + 4);
        gv[2] = *(const float4*)(p + 8);
        gv[3] = *(const float4*)(p + 12);
    };

    ldg_g(u0);
    issue_y(0, u0); cpa_commit();
    if (u0 + 1 < u1) issue_y(1, u0 + 1);
    cpa_commit();

    for (int u = u0; u < u1; u++) {
        int it = u - u0;
        uint32_t gbuf = sb + SM_GB + (it & 1) * GB_SIZE;
        uint32_t ybuf = sb + SM_Y + (it % 3) * Y_STAGE;

        int mtu = u >> 7;
        if (mtu != cur_mt) {                     // <=1 boundary per CTA
            flush();
            cur_mt = mtu;
            m0 = mtu * TM;
            a_reg = g_a[m0 + rb];
        }

        // ---- G pass: exact fp32 deg terms + bf16 convert + STS ----
        {
            int kk = (u & 127) * TK;
            const float4* bp = (const float4*)(g_b + kk + ch * 16);
            float sg = 0.f, db = 0.f;
            uint32_t pk[8];
#pragma unroll
            for (int i = 0; i < 4; i++) {
                float4 v = gv[i];
                float4 bb = bp[i];
                sg += v.x + v.y + v.z + v.w;
                db += v.x * bb.x + v.y * bb.y + v.z * bb.z + v.w * bb.w;
                __nv_bfloat162 h0 = __float22bfloat162_rn(make_float2(v.x, v.y));
                __nv_bfloat162 h1 = __float22bfloat162_rn(make_float2(v.z, v.w));
                pk[2 * i] = *(uint32_t*)&h0;
                pk[2 * i + 1] = *(uint32_t*)&h1;
            }
            s_deg += a_reg * sg + db;
            int c0 = ch * 2;
            uint32_t ad0 = gbuf + rb * 128 + ((c0 ^ (rb & 7)) << 4);
            uint32_t ad1 = gbuf + rb * 128 + (((c0 + 1) ^ (rb & 7)) << 4);
            asm volatile("st.shared.v4.b32 [%0], {%1,%2,%3,%4};" ::"r"(ad0),
                         "r"(pk[0]), "r"(pk[1]), "r"(pk[2]), "r"(pk[3]));
            asm volatile("st.shared.v4.b32 [%0], {%1,%2,%3,%4};" ::"r"(ad1),
                         "r"(pk[4]), "r"(pk[5]), "r"(pk[6]), "r"(pk[7]));
        }

        if (u + 1 < u1) ldg_g(u + 1);

        asm volatile("cp.async.wait_group 1;\n" ::: "memory");
        __syncthreads();

        if (u + 2 < u1) issue_y((it + 2) % 3, u + 2);
        cpa_commit();

        // ---- MMA: acc += G[qm-quarter, k-half] * Y^T[qn-half] ----
#pragma unroll
        for (int ksb = 0; ksb < 2; ksb++) {
            int cb = (kbase + ksb * 16) >> 3;
            uint32_t A[2][4];
#pragma unroll
            for (int ms = 0; ms < 2; ms++) {
                int r = qm * 32 + ms * 16 + (lane & 15);
                int c = cb + (lane >> 4);
                ldsm_x4(A[ms], gbuf + r * 128 + ((c ^ (r & 7)) << 4));
            }
#pragma unroll
            for (int p = 0; p < 4; p++) {
                int r = qn * 64 + p * 16 + (lane & 7) + ((lane >> 4) << 3);
                int c = cb + ((lane >> 3) & 1);
                uint32_t mm[4];
                ldsm_x4(mm, ybuf + r * 128 + ((c ^ (r & 7)) << 4));
#pragma unroll
                for (int ms = 0; ms < 2; ms++) {
                    asm volatile(
                        "mma.sync.aligned.m16n8k16.row.col.f32.bf16.bf16.f32 "
                        "{%0,%1,%2,%3},{%4,%5,%6,%7},{%8,%9},{%0,%1,%2,%3};\n"
                        : "+f"(acc[ms][2 * p][0]), "+f"(acc[ms][2 * p][1]),
                          "+f"(acc[ms][2 * p][2]), "+f"(acc[ms][2 * p][3])
                        : "r"(A[ms][0]), "r"(A[ms][1]), "r"(A[ms][2]),
                          "r"(A[ms][3]), "r"(mm[0]), "r"(mm[1]));
                    asm volatile(
                        "mma.sync.aligned.m16n8k16.row.col.f32.bf16.bf16.f32 "
                        "{%0,%1,%2,%3},{%4,%5,%6,%7},{%8,%9},{%0,%1,%2,%3};\n"
                        : "+f"(acc[ms][2 * p + 1][0]), "+f"(acc[ms][2 * p + 1][1]),
                          "+f"(acc[ms][2 * p + 1][2]), "+f"(acc[ms][2 * p + 1][3])
                        : "r"(A[ms][0]), "r"(A[ms][1]), "r"(A[ms][2]),
                          "r"(A[ms][3]), "r"(mm[2]), "r"(mm[3]));
                }
            }
        }
    }

    // ---- final flush + reduce + last-CTA finalize ----
    flush();
    float tot = s_deg - 2.f * s_cross;
#pragma unroll
    for (int o = 16; o > 0; o >>= 1) tot += __shfl_down_sync(0xffffffffu, tot, o);
    if (lane == 0) wsum[wid] = tot;
    __syncthreads();
    if (t == 0) {
        float s = 0.f;
#pragma unroll
        for (int i = 0; i < 16; i++) s += wsum[i];
        atomicAdd(&g_acc, (double)s);
        __threadfence();
        unsigned prev = atomicAdd(&g_done, 1u);
        if (prev == GRID - 1) {
            double v = atomicAdd(&g_acc, 0.0);
            out[0] = (float)(v / (double)((long long)m * (long long)n));
            g_acc = 0.0;                         // reset for graph replay
            g_done = 0u;
        }
    }
}

extern "C" void kernel_launch(void* const* d_in, const int* in_sizes, int n_in,
                              void* d_out, int out_size) {
    const float* G = (const float*)d_in[0];   // sub_graph [m,n]
    const float* X = (const float*)d_in[1];   // sub_x [m,128]
    const float* Y = (const float*)d_in[2];   // all_x [n,128]
    int m = in_sizes[1] / DD;
    int n = in_sizes[2] / DD;

    cudaFuncSetAttribute(main_kernel, cudaFuncAttributeMaxDynamicSharedMemorySize,
                         SMEM_TOTAL);

    prep_kernel<<<(m + n) / 32, 256>>>(X, Y, m, n);
    main_kernel<<<GRID, NTHREADS, SMEM_TOTAL>>>(G, X, (float*)d_out, m, n);
}

// round 14
// speedup vs baseline: 1.1450x; 1.1450x over previous
#include <cuda_runtime.h>
#include <cuda_bf16.h>
#include <cstdint>

#define DD 128
#define TMC 64                         // CTA m-tile
#define TK 64
#define NTHREADS 256
#define GRID 296                       // 2 CTAs per SM

// ---- device scratch (no allocations allowed) ----
__device__ double g_acc;
__device__ unsigned int g_done;
__device__ float g_a[4096];                    // ||sub_x_i||^2
__device__ float g_b[8192];                    // ||all_x_j||^2
__device__ __align__(16) __nv_bfloat16 g_Yt[128 * 8192];  // all_x^T bf16: [d][n]

// ---- dynamic smem layout (bytes) ----
#define Y_STAGE 16384                  // 128 rows * 128B bf16, XOR-swizzled
#define GB_SIZE 8192                   // 64 rows * 128B bf16, XOR-swizzled
#define SM_Y 0                         // 3 stages
#define SM_GB (3 * Y_STAGE)            // 2 buffers
#define SM_WSUM (SM_GB + 2 * GB_SIZE)
#define SMEM_TOTAL (SM_WSUM + 64)      // 65600 per CTA -> 2 fit in 227KB

// ---------------------------------------------------------------------------
static __device__ __forceinline__ uint32_t smem_u32(const void* p) {
    return (uint32_t)__cvta_generic_to_shared(p);
}
static __device__ __forceinline__ void cpa16(uint32_t smem_dst, const void* gsrc) {
    asm volatile("cp.async.cg.shared.global [%0], [%1], 16;\n" ::"r"(smem_dst), "l"(gsrc));
}
static __device__ __forceinline__ void cpa_commit() {
    asm volatile("cp.async.commit_group;\n" ::: "memory");
}
static __device__ __forceinline__ void ldsm_x4(uint32_t* r, uint32_t addr) {
    asm volatile("ldmatrix.sync.aligned.m8n8.x4.shared.b16 {%0,%1,%2,%3}, [%4];"
                 : "=r"(r[0]), "=r"(r[1]), "=r"(r[2]), "=r"(r[3]) : "r"(addr));
}

// ---------------------------------------------------------------------------
// prep: per-row sumsq -> g_a/g_b, bf16 transpose of all_x -> g_Yt.
// One block = 32 rows. Also zeros g_acc / g_done.
// ---------------------------------------------------------------------------
__global__ void prep_kernel(const float* __restrict__ subx,
                            const float* __restrict__ allx, int m, int n) {
    __shared__ float ys[32 * 132];
    int b = blockIdx.x;
    int t = threadIdx.x;
    if (b == 0 && t == 0) { g_acc = 0.0; g_done = 0u; }
    int nb_y = n / 32;
    bool isY = b < nb_y;
    const float* src = isY ? allx : subx;
    int r0 = isY ? b * 32 : (b - nb_y) * 32;

#pragma unroll
    for (int i = 0; i < 4; i++) {
        int ci = i * 256 + t;
        int rl = ci >> 5, c4 = ci & 31;
        float4 v = *(const float4*)(src + (size_t)(r0 + rl) * DD + c4 * 4);
        *(float4*)(ys + rl * 132 + c4 * 4) = v;
    }
    __syncthreads();

    {
        int rl = t >> 3, sub = t & 7;
        const float* row = ys + rl * 132 + sub * 16;
        float s = 0.f;
#pragma unroll
        for (int i = 0; i < 16; i++) { float v = row[i]; s += v * v; }
        s += __shfl_down_sync(0xffffffffu, s, 4, 8);
        s += __shfl_down_sync(0xffffffffu, s, 2, 8);
        s += __shfl_down_sync(0xffffffffu, s, 1, 8);
        if (sub == 0) { if (isY) g_b[r0 + rl] = s; else g_a[r0 + rl] = s; }
    }

    if (isY) {
        int d = t >> 1, half = t & 1;
        uint32_t pk[8];
#pragma unroll
        for (int i = 0; i < 8; i++) {
            int r = half * 16 + i * 2;
            float f0 = ys[r * 132 + d];
            float f1 = ys[(r + 1) * 132 + d];
            __nv_bfloat162 h = __float22bfloat162_rn(make_float2(f0, f1));
            pk[i] = *(uint32_t*)&h;
        }
        uint4* dst = (uint4*)(g_Yt + (size_t)d * n + r0 + half * 16);
        dst[0] = make_uint4(pk[0], pk[1], pk[2], pk[3]);
        dst[1] = make_uint4(pk[4], pk[5], pk[6], pk[7]);
    }
}

// ---------------------------------------------------------------------------
// main kernel: 296 CTAs (2/SM, independent barrier domains), 256 thr each.
// CTA tile = 64m x 128n per 64-k unit. Warp w = (qn 0..3, kh 0..1):
// 64m x 32n x k-half. acc = 64 regs.
// Units u = mt*128 + kt (mt 0..63), contiguous 27/28-unit ranges, flush at
// mt boundaries. Gpass thread: row rb = t>>2 (0..63), chunk ch = t&3.
// ---------------------------------------------------------------------------
__global__ __launch_bounds__(NTHREADS, 2)
void main_kernel(const float* __restrict__ G, const float* __restrict__ X,
                 float* __restrict__ out, int m, int n) {
    extern __shared__ char smem[];
    const uint32_t sb = smem_u32(smem);
    float* wsum = (float*)(smem + SM_WSUM);

    const int t = threadIdx.x;
    const int bid = blockIdx.x;
    const int wid = t >> 5, lane = t & 31;
    const int g = lane >> 2, tg = lane & 3;
    const int qn = wid & 3, kh = wid >> 2;
    const int kbase = kh * 32;
    const int rb = t >> 2, ch = t & 3;           // Gpass: row, 16-float chunk

    const int U = (m / TMC) * (n / TK);          // 8192
    const int base = U / GRID, rem = U - base * GRID;   // 27, 200
    const int u0 = (bid < rem) ? bid * (base + 1)
                               : rem * (base + 1) + (bid - rem) * base;
    const int u1 = u0 + ((bid < rem) ? base + 1 : base);

    int cur_mt = u0 >> 7;                        // 128 k-units per mt
    int m0 = cur_mt * TMC;

    float a_reg = g_a[m0 + rb];

    float acc[4][4][4];                          // [ms][ns][frag] = 64 regs
#pragma unroll
    for (int i = 0; i < 4; i++)
#pragma unroll
        for (int j = 0; j < 4; j++)
#pragma unroll
            for (int c = 0; c < 4; c++) acc[i][j][c] = 0.f;
    float s_deg = 0.f, s_cross = 0.f;

    auto flush = [&]() {
#pragma unroll
        for (int ms = 0; ms < 4; ms++) {
            int r1 = m0 + ms * 16 + g;
#pragma unroll
            for (int ns = 0; ns < 4; ns++) {
                int col = qn * 32 + ns * 8 + 2 * tg;
                float2 x0 = *(const float2*)(X + (size_t)r1 * DD + col);
                float2 x1 = *(const float2*)(X + (size_t)(r1 + 8) * DD + col);
                s_cross += acc[ms][ns][0] * x0.x + acc[ms][ns][1] * x0.y +
                           acc[ms][ns][2] * x1.x + acc[ms][ns][3] * x1.y;
                acc[ms][ns][0] = 0.f; acc[ms][ns][1] = 0.f;
                acc[ms][ns][2] = 0.f; acc[ms][ns][3] = 0.f;
            }
        }
    };

    auto issue_y = [&](int stage, int u) {
        int kk = (u & 127) * TK;
        uint32_t yv = sb + SM_Y + stage * Y_STAGE;
#pragma unroll
        for (int i = 0; i < 4; i++) {
            int ci = i * NTHREADS + t;
            int r = ci >> 3, c = ci & 7;
            cpa16(yv + r * 128 + ((c ^ (r & 7)) << 4),
                  g_Yt + (size_t)r * n + kk + c * 8);
        }
    };

    // G fp32: thread holds 16 floats of its row (one unit ahead)
    float4 gv[4];
    auto ldg_g = [&](int u) {
        int mm0 = (u >> 7) * TMC;
        int kk = (u & 127) * TK;
        const float* p = G + (size_t)(mm0 + rb) * n + kk + ch * 16;
        gv[0] = *(const float4*)p;
        gv[1] = *(const float4*)(p + 4);
        gv[2] = *(const float4*)(p + 8);
        gv[3] = *(const float4*)(p + 12);
    };

    ldg_g(u0);
    issue_y(0, u0); cpa_commit();
    if (u0 + 1 < u1) issue_y(1, u0 + 1);
    cpa_commit();

    for (int u = u0; u < u1; u++) {
        int it = u - u0;
        uint32_t gbuf = sb + SM_GB + (it & 1) * GB_SIZE;
        uint32_t ybuf = sb + SM_Y + (it % 3) * Y_STAGE;

        int mtu = u >> 7;
        if (mtu != cur_mt) {                     // <=1 boundary per CTA
            flush();
            cur_mt = mtu;
            m0 = mtu * TMC;
            a_reg = g_a[m0 + rb];
        }

        // ---- G pass: exact fp32 deg terms + bf16 convert + STS ----
        {
            int kk = (u & 127) * TK;
            const float4* bp = (const float4*)(g_b + kk + ch * 16);
            float sg = 0.f, db = 0.f;
            uint32_t pk[8];
#pragma unroll
            for (int i = 0; i < 4; i++) {
                float4 v = gv[i];
                float4 bb = bp[i];
                sg += v.x + v.y + v.z + v.w;
                db += v.x * bb.x + v.y * bb.y + v.z * bb.z + v.w * bb.w;
                __nv_bfloat162 h0 = __float22bfloat162_rn(make_float2(v.x, v.y));
                __nv_bfloat162 h1 = __float22bfloat162_rn(make_float2(v.z, v.w));
                pk[2 * i] = *(uint32_t*)&h0;
                pk[2 * i + 1] = *(uint32_t*)&h1;
            }
            s_deg += a_reg * sg + db;
            int c0 = ch * 2;
            uint32_t ad0 = gbuf + rb * 128 + ((c0 ^ (rb & 7)) << 4);
            uint32_t ad1 = gbuf + rb * 128 + (((c0 + 1) ^ (rb & 7)) << 4);
            asm volatile("st.shared.v4.b32 [%0], {%1,%2,%3,%4};" ::"r"(ad0),
                         "r"(pk[0]), "r"(pk[1]), "r"(pk[2]), "r"(pk[3]));
            asm volatile("st.shared.v4.b32 [%0], {%1,%2,%3,%4};" ::"r"(ad1),
                         "r"(pk[4]), "r"(pk[5]), "r"(pk[6]), "r"(pk[7]));
        }

        if (u + 1 < u1) ldg_g(u + 1);

        asm volatile("cp.async.wait_group 1;\n" ::: "memory");
        __syncthreads();

        if (u + 2 < u1) issue_y((it + 2) % 3, u + 2);
        cpa_commit();

        // ---- MMA: acc += G[64m, k-half] * Y^T[qn-quarter] ----
#pragma unroll
        for (int ksb = 0; ksb < 2; ksb++) {
            int cb = (kbase + ksb * 16) >> 3;
            uint32_t A[4][4];
#pragma unroll
            for (int ms = 0; ms < 4; ms++) {
                int r = ms * 16 + (lane & 15);
                int c = cb + (lane >> 4);
                ldsm_x4(A[ms], gbuf + r * 128 + ((c ^ (r & 7)) << 4));
            }
#pragma unroll
            for (int p = 0; p < 2; p++) {
                int r = qn * 32 + p * 16 + (lane & 7) + ((lane >> 4) << 3);
                int c = cb + ((lane >> 3) & 1);
                uint32_t mm[4];
                ldsm_x4(mm, ybuf + r * 128 + ((c ^ (r & 7)) << 4));
#pragma unroll
                for (int ms = 0; ms < 4; ms++) {
                    asm volatile(
                        "mma.sync.aligned.m16n8k16.row.col.f32.bf16.bf16.f32 "
                        "{%0,%1,%2,%3},{%4,%5,%6,%7},{%8,%9},{%0,%1,%2,%3};\n"
                        : "+f"(acc[ms][2 * p][0]), "+f"(acc[ms][2 * p][1]),
                          "+f"(acc[ms][2 * p][2]), "+f"(acc[ms][2 * p][3])
                        : "r"(A[ms][0]), "r"(A[ms][1]), "r"(A[ms][2]),
                          "r"(A[ms][3]), "r"(mm[0]), "r"(mm[1]));
                    asm volatile(
                        "mma.sync.aligned.m16n8k16.row.col.f32.bf16.bf16.f32 "
                        "{%0,%1,%2,%3},{%4,%5,%6,%7},{%8,%9},{%0,%1,%2,%3};\n"
                        : "+f"(acc[ms][2 * p + 1][0]), "+f"(acc[ms][2 * p + 1][1]),
                          "+f"(acc[ms][2 * p + 1][2]), "+f"(acc[ms][2 * p + 1][3])
                        : "r"(A[ms][0]), "r"(A[ms][1]), "r"(A[ms][2]),
                          "r"(A[ms][3]), "r"(mm[2]), "r"(mm[3]));
                }
            }
        }
    }

    // ---- final flush + reduce + last-CTA finalize ----
    flush();
    float tot = s_deg - 2.f * s_cross;
#pragma unroll
    for (int o = 16; o > 0; o >>= 1) tot += __shfl_down_sync(0xffffffffu, tot, o);
    if (lane == 0) wsum[wid] = tot;
    __syncthreads();
    if (t == 0) {
        float s = 0.f;
#pragma unroll
        for (int i = 0; i < 8; i++) s += wsum[i];
        atomicAdd(&g_acc, (double)s);
        __threadfence();
        unsigned prev = atomicAdd(&g_done, 1u);
        if (prev == GRID - 1) {
            double v = atomicAdd(&g_acc, 0.0);
            out[0] = (float)(v / (double)((long long)m * (long long)n));
            g_acc = 0.0;                         // reset for graph replay
            g_done = 0u;
        }
    }
}

extern "C" void kernel_launch(void* const* d_in, const int* in_sizes, int n_in,
                              void* d_out, int out_size) {
    const float* G = (const float*)d_in[0];   // sub_graph [m,n]
    const float* X = (const float*)d_in[1];   // sub_x [m,128]
    const float* Y = (const float*)d_in[2];   // all_x [n,128]
    int m = in_sizes[1] / DD;
    int n = in_sizes[2] / DD;

    cudaFuncSetAttribute(main_kernel, cudaFuncAttributeMaxDynamicSharedMemorySize,
                         SMEM_TOTAL);

    prep_kernel<<<(m + n) / 32, 256>>>(X, Y, m, n);
    main_kernel<<<GRID, NTHREADS, SMEM_TOTAL>>>(G, X, (float*)d_out, m, n);
}

// round 15
// speedup vs baseline: 1.6138x; 1.4094x over previous
#include <cuda_runtime.h>
#include <cuda_bf16.h>
#include <cstdint>

#define DD 128
#define TM 128
#define TK 64
#define NTHREADS 256
#define GRID 148

// ---- device scratch (no allocations allowed) ----
__device__ double g_acc;
__device__ unsigned int g_done;
__device__ float g_a[4096];                    // ||sub_x_i||^2
__device__ float g_b[8192];                    // ||all_x_j||^2
__device__ __align__(16) __nv_bfloat16 g_Yt[128 * 8192];   // all_x^T bf16: [d][n]
__device__ __align__(16) __nv_bfloat16 g_Yaux[8 * 8192];   // aux rows: 1, b_j, 0...

// ---- dynamic smem layout (bytes) ----
#define Y_STAGE 17408                  // 136 rows * 128B bf16 (128 Y + 8 aux)
#define GB_SIZE 16384
#define SM_Y 0                         // 3 stages
#define SM_GB (3 * Y_STAGE)            // 2 buffers
#define SM_WSUM (SM_GB + 2 * GB_SIZE)
#define SMEM_TOTAL (SM_WSUM + 64)

// ---------------------------------------------------------------------------
static __device__ __forceinline__ uint32_t smem_u32(const void* p) {
    return (uint32_t)__cvta_generic_to_shared(p);
}
static __device__ __forceinline__ void cpa16(uint32_t smem_dst, const void* gsrc) {
    asm volatile("cp.async.cg.shared.global [%0], [%1], 16;\n" ::"r"(smem_dst), "l"(gsrc));
}
static __device__ __forceinline__ void cpa_commit() {
    asm volatile("cp.async.commit_group;\n" ::: "memory");
}
static __device__ __forceinline__ void ldsm_x4(uint32_t* r, uint32_t addr) {
    asm volatile("ldmatrix.sync.aligned.m8n8.x4.shared.b16 {%0,%1,%2,%3}, [%4];"
                 : "=r"(r[0]), "=r"(r[1]), "=r"(r[2]), "=r"(r[3]) : "r"(addr));
}
static __device__ __forceinline__ void ldsm_x2(uint32_t* r, uint32_t addr) {
    asm volatile("ldmatrix.sync.aligned.m8n8.x2.shared.b16 {%0,%1}, [%2];"
                 : "=r"(r[0]), "=r"(r[1]) : "r"(addr));
}

// ---------------------------------------------------------------------------
// prep: per-row sumsq -> g_a/g_b, bf16 transpose of all_x -> g_Yt, and the
// aux strip g_Yaux (row0 = 1, row1 = bf16(b_j), rows 2-7 = 0).
// One block = 32 rows. Also zeros g_acc / g_done.
// ---------------------------------------------------------------------------
__global__ void prep_kernel(const float* __restrict__ subx,
                            const float* __restrict__ allx, int m, int n) {
    __shared__ float ys[32 * 132];
    int b = blockIdx.x;
    int t = threadIdx.x;
    if (b == 0 && t == 0) { g_acc = 0.0; g_done = 0u; }
    int nb_y = n / 32;
    bool isY = b < nb_y;
    const float* src = isY ? allx : subx;
    int r0 = isY ? b * 32 : (b - nb_y) * 32;

#pragma unroll
    for (int i = 0; i < 4; i++) {
        int ci = i * 256 + t;
        int rl = ci >> 5, c4 = ci & 31;
        float4 v = *(const float4*)(src + (size_t)(r0 + rl) * DD + c4 * 4);
        *(float4*)(ys + rl * 132 + c4 * 4) = v;
    }
    __syncthreads();

    {
        int rl = t >> 3, sub = t & 7;
        const float* row = ys + rl * 132 + sub * 16;
        float s = 0.f;
#pragma unroll
        for (int i = 0; i < 16; i++) { float v = row[i]; s += v * v; }
        s += __shfl_down_sync(0xffffffffu, s, 4, 8);
        s += __shfl_down_sync(0xffffffffu, s, 2, 8);
        s += __shfl_down_sync(0xffffffffu, s, 1, 8);
        if (sub == 0) {
            if (isY) {
                g_b[r0 + rl] = s;
                g_Yaux[(size_t)1 * n + r0 + rl] = __float2bfloat16(s);
            } else {
                g_a[r0 + rl] = s;
            }
        }
    }

    if (isY) {
        // aux rows 0 (ones) and 2-7 (zeros)
        {
            int rr = t >> 5, cc = t & 31;
            if (rr == 0) g_Yaux[(size_t)0 * n + r0 + cc] = __float2bfloat16(1.0f);
            else if (rr >= 2) g_Yaux[(size_t)rr * n + r0 + cc] = __float2bfloat16(0.0f);
        }
        int d = t >> 1, half = t & 1;
        uint32_t pk[8];
#pragma unroll
        for (int i = 0; i < 8; i++) {
            int r = half * 16 + i * 2;
            float f0 = ys[r * 132 + d];
            float f1 = ys[(r + 1) * 132 + d];
            __nv_bfloat162 h = __float22bfloat162_rn(make_float2(f0, f1));
            pk[i] = *(uint32_t*)&h;
        }
        uint4* dst = (uint4*)(g_Yt + (size_t)d * n + r0 + half * 16);
        dst[0] = make_uint4(pk[0], pk[1], pk[2], pk[3]);
        dst[1] = make_uint4(pk[4], pk[5], pk[6], pk[7]);
    }
}

// ---------------------------------------------------------------------------
// main kernel: r6 structure; deg terms via aux MMA columns (cols 128=1, 129=b).
// Warp w = (qm, qn, kh): 64x64 block, k-half; qn==0 warps also compute the
// 8-wide aux tile into acc_aux.
// ---------------------------------------------------------------------------
__global__ __launch_bounds__(NTHREADS, 1)
void main_kernel(const float* __restrict__ G, const float* __restrict__ X,
                 float* __restrict__ out, int m, int n) {
    extern __shared__ char smem[];
    const uint32_t sb = smem_u32(smem);
    float* wsum = (float*)(smem + SM_WSUM);

    const int t = threadIdx.x;
    const int bid = blockIdx.x;
    const int wid = t >> 5, lane = t & 31;
    const int g = lane >> 2, tg = lane & 3;
    const int qm = wid & 1, qn = (wid >> 1) & 1, kh = wid >> 2;
    const int kbase = kh * 32;
    const int rb = t >> 3, ch = t & 7;

    const int U = (m / TM) * (n / TK);           // 4096
    const int base = U / GRID, rem = U - base * GRID;
    const int u0 = (bid < rem) ? bid * (base + 1)
                               : rem * (base + 1) + (bid - rem) * base;
    const int u1 = u0 + ((bid < rem) ? base + 1 : base);

    int cur_mt = u0 >> 7;
    int m0 = cur_mt * TM;

    float acc[4][8][4];
#pragma unroll
    for (int i = 0; i < 4; i++)
#pragma unroll
        for (int j = 0; j < 8; j++)
#pragma unroll
            for (int c = 0; c < 4; c++) acc[i][j][c] = 0.f;
    float acc_aux[4][4];                         // aux n8 tile (qn==0 warps)
#pragma unroll
    for (int i = 0; i < 4; i++)
#pragma unroll
        for (int c = 0; c < 4; c++) acc_aux[i][c] = 0.f;
    float s_deg = 0.f, s_cross = 0.f;

    // ---- flush: cross from acc, deg from acc_aux; reset both ----
    auto flush = [&]() {
#pragma unroll
        for (int ms = 0; ms < 4; ms++) {
            int r1 = m0 + qm * 64 + ms * 16 + g;
#pragma unroll
            for (int ns = 0; ns < 8; ns++) {
                int col = qn * 64 + ns * 8 + 2 * tg;
                float2 x0 = *(const float2*)(X + (size_t)r1 * DD + col);
                float2 x1 = *(const float2*)(X + (size_t)(r1 + 8) * DD + col);
                s_cross += acc[ms][ns][0] * x0.x + acc[ms][ns][1] * x0.y +
                           acc[ms][ns][2] * x1.x + acc[ms][ns][3] * x1.y;
                acc[ms][ns][0] = 0.f; acc[ms][ns][1] = 0.f;
                acc[ms][ns][2] = 0.f; acc[ms][ns][3] = 0.f;
            }
            // aux cols: 128+2tg (tg==0 -> cols 128,129 real; others zero acc)
            float ga0 = g_a[r1];
            float ga8 = g_a[r1 + 8];
            s_deg += acc_aux[ms][0] * ga0 + acc_aux[ms][1] +
                     acc_aux[ms][2] * ga8 + acc_aux[ms][3];
            acc_aux[ms][0] = 0.f; acc_aux[ms][1] = 0.f;
            acc_aux[ms][2] = 0.f; acc_aux[ms][3] = 0.f;
        }
    };

    auto issue_y = [&](int stage, int u) {
        int kk = (u & 127) * TK;
        uint32_t yv = sb + SM_Y + stage * Y_STAGE;
#pragma unroll
        for (int i = 0; i < 4; i++) {
            int ci = i * NTHREADS + t;
            int r = ci >> 3, c = ci & 7;
            cpa16(yv + r * 128 + ((c ^ (r & 7)) << 4),
                  g_Yt + (size_t)r * n + kk + c * 8);
        }
        if (t < 64) {                            // aux rows 128-135
            int r = 128 + (t >> 3), c = t & 7;
            cpa16(yv + r * 128 + ((c ^ (r & 7)) << 4),
                  g_Yaux + (size_t)(r - 128) * n + kk + c * 8);
        }
    };

    float4 gv[8];
    auto ldg_g = [&](int u) {
        int mm0 = (u >> 7) * TM;
        int kk = (u & 127) * TK;
#pragma unroll
        for (int rr = 0; rr < 4; rr++) {
            const float* p = G + (size_t)(mm0 + rb + 32 * rr) * n + kk + ch * 8;
            gv[2 * rr] = *(const float4*)p;
            gv[2 * rr + 1] = *(const float4*)(p + 4);
        }
    };

    ldg_g(u0);
    issue_y(0, u0); cpa_commit();
    if (u0 + 1 < u1) issue_y(1, u0 + 1);
    cpa_commit();

    for (int u = u0; u < u1; u++) {
        int it = u - u0;
        uint32_t gbuf = sb + SM_GB + (it & 1) * GB_SIZE;
        uint32_t ybuf = sb + SM_Y + (it % 3) * Y_STAGE;

        int mtu = u >> 7;
        if (mtu != cur_mt) {                     // <=1 boundary per CTA
            flush();
            cur_mt = mtu;
            m0 = mtu * TM;
        }

        // ---- G pass: pure fp32 -> bf16 convert + STS (no deg math) ----
#pragma unroll
        for (int rr = 0; rr < 4; rr++) {
            float4 v0 = gv[2 * rr], v1 = gv[2 * rr + 1];
            __nv_bfloat162 h0 = __float22bfloat162_rn(make_float2(v0.x, v0.y));
            __nv_bfloat162 h1 = __float22bfloat162_rn(make_float2(v0.z, v0.w));
            __nv_bfloat162 h2 = __float22bfloat162_rn(make_float2(v1.x, v1.y));
            __nv_bfloat162 h3 = __float22bfloat162_rn(make_float2(v1.z, v1.w));
            int r = rb + 32 * rr;
            uint32_t ad = gbuf + r * 128 + ((ch ^ (r & 7)) << 4);
            asm volatile("st.shared.v4.b32 [%0], {%1,%2,%3,%4};" ::"r"(ad),
                         "r"(*(uint32_t*)&h0), "r"(*(uint32_t*)&h1),
                         "r"(*(uint32_t*)&h2), "r"(*(uint32_t*)&h3));
        }

        if (u + 1 < u1) ldg_g(u + 1);

        asm volatile("cp.async.wait_group 1;\n" ::: "memory");
        __syncthreads();

        if (u + 2 < u1) issue_y((it + 2) % 3, u + 2);
        cpa_commit();

        // ---- MMA: acc += G[qm-half, k-half] * Y^T[qn-half] (+ aux) ----
#pragma unroll
        for (int ksb = 0; ksb < 2; ksb++) {
            int cb = (kbase + ksb * 16) >> 3;
            uint32_t A[4][4];
#pragma unroll
            for (int ms = 0; ms < 4; ms++) {
                int r = qm * 64 + ms * 16 + (lane & 15);
                int c = cb + (lane >> 4);
                ldsm_x4(A[ms], gbuf + r * 128 + ((c ^ (r & 7)) << 4));
            }
            uint32_t B[8][2];
#pragma unroll
            for (int p = 0; p < 4; p++) {
                int r = qn * 64 + p * 16 + (lane & 7) + ((lane >> 4) << 3);
                int c = cb + ((lane >> 3) & 1);
                uint32_t mm[4];
                ldsm_x4(mm, ybuf + r * 128 + ((c ^ (r & 7)) << 4));
                B[2 * p][0] = mm[0]; B[2 * p][1] = mm[1];
                B[2 * p + 1][0] = mm[2]; B[2 * p + 1][1] = mm[3];
            }
#pragma unroll
            for (int ms = 0; ms < 4; ms++)
#pragma unroll
                for (int ns = 0; ns < 8; ns++) {
                    asm volatile(
                        "mma.sync.aligned.m16n8k16.row.col.f32.bf16.bf16.f32 "
                        "{%0,%1,%2,%3},{%4,%5,%6,%7},{%8,%9},{%0,%1,%2,%3};\n"
                        : "+f"(acc[ms][ns][0]), "+f"(acc[ms][ns][1]),
                          "+f"(acc[ms][ns][2]), "+f"(acc[ms][ns][3])
                        : "r"(A[ms][0]), "r"(A[ms][1]), "r"(A[ms][2]),
                          "r"(A[ms][3]), "r"(B[ns][0]), "r"(B[ns][1]));
                }
            if (qn == 0) {                       // aux tile: cols 128-135
                int r = 128 + (lane & 7);
                int c = cb + ((lane >> 3) & 1);  // lanes 0-15 give both cols
                uint32_t aux[2];
                ldsm_x2(aux, ybuf + r * 128 + ((c ^ (r & 7)) << 4));
#pragma unroll
                for (int ms = 0; ms < 4; ms++) {
                    asm volatile(
                        "mma.sync.aligned.m16n8k16.row.col.f32.bf16.bf16.f32 "
                        "{%0,%1,%2,%3},{%4,%5,%6,%7},{%8,%9},{%0,%1,%2,%3};\n"
                        : "+f"(acc_aux[ms][0]), "+f"(acc_aux[ms][1]),
                          "+f"(acc_aux[ms][2]), "+f"(acc_aux[ms][3])
                        : "r"(A[ms][0]), "r"(A[ms][1]), "r"(A[ms][2]),
                          "r"(A[ms][3]), "r"(aux[0]), "r"(aux[1]));
                }
            }
        }
    }

    // ---- final flush + reduce + last-CTA finalize ----
    flush();
    float tot = s_deg - 2.f * s_cross;
#pragma unroll
    for (int o = 16; o > 0; o >>= 1) tot += __shfl_down_sync(0xffffffffu, tot, o);
    if (lane == 0) wsum[wid] = tot;
    __syncthreads();
    if (t == 0) {
        float s = 0.f;
#pragma unroll
        for (int i = 0; i < 8; i++) s += wsum[i];
        atomicAdd(&g_acc, (double)s);
        __threadfence();
        unsigned prev = atomicAdd(&g_done, 1u);
        if (prev == GRID - 1) {
            double v = atomicAdd(&g_acc, 0.0);
            out[0] = (float)(v / (double)((long long)m * (long long)n));
            g_acc = 0.0;                         // reset for graph replay
            g_done = 0u;
        }
    }
}

extern "C" void kernel_launch(void* const* d_in, const int* in_sizes, int n_in,
                              void* d_out, int out_size) {
    const float* G = (const float*)d_in[0];   // sub_graph [m,n]
    const float* X = (const float*)d_in[1];   // sub_x [m,128]
    const float* Y = (const float*)d_in[2];   // all_x [n,128]
    int m = in_sizes[1] / DD;
    int n = in_sizes[2] / DD;

    cudaFuncSetAttribute(main_kernel, cudaFuncAttributeMaxDynamicSharedMemorySize,
                         SMEM_TOTAL);

    prep_kernel<<<(m + n) / 32, 256>>>(X, Y, m, n);
    main_kernel<<<GRID, NTHREADS, SMEM_TOTAL>>>(G, X, (float*)d_out, m, n);
}